// round 1
// baseline (speedup 1.0000x reference)
#include <cuda_runtime.h>
#include <cuda_bf16.h>

// MeanSquaredError2: loss = [ sum(h^2) + sum_{vis}(1 - 2*h[b,j,xi,yi]) ] * 2/size
// o input is unused by the reference. Pure HBM-bound streaming reduction.

#define COLS 14
#define CELLS (COLS * COLS)   // 196

__global__ void mse_init_kernel(float* out) {
    if (blockIdx.x == 0 && threadIdx.x == 0) out[0] = 0.0f;
}

__global__ __launch_bounds__(256) void mse_reduce_kernel(
    const float4* __restrict__ h4, long long n4,
    const float*  __restrict__ h,
    const float*  __restrict__ t,
    const int*    __restrict__ v,
    int npairs, float scale, float* __restrict__ out)
{
    const int tid  = threadIdx.x;
    const long long gid = (long long)blockIdx.x * blockDim.x + tid;
    const long long gstride = (long long)gridDim.x * blockDim.x;

    float local = 0.0f;

    // Main streaming pass over h as float4 (coalesced, high MLP from unroll).
    for (long long i = gid; i < n4; i += gstride) {
        float4 x = __ldg(&h4[i]);
        local += x.x * x.x + x.y * x.y + x.z * x.z + x.w * x.w;
    }

    // One-hot correction: one (b,j) pair per global thread (npairs < gridDim*blockDim).
    if (gid < npairs) {
        int p = (int)gid;
        if (__ldg(&v[p]) == 1) {
            float tx = __ldg(&t[2 * p]);
            float ty = __ldg(&t[2 * p + 1]);
            int xi = (int)(tx * (float)COLS);
            int yi = (int)(ty * (float)COLS);
            xi = min(max(xi, 0), COLS - 1);
            yi = min(max(yi, 0), COLS - 1);
            float hv = __ldg(&h[(long long)p * CELLS + xi * COLS + yi]);
            local += 1.0f - 2.0f * hv;
        }
    }

    // Warp reduce
    #pragma unroll
    for (int off = 16; off > 0; off >>= 1)
        local += __shfl_xor_sync(0xFFFFFFFFu, local, off);

    // Block reduce via shared
    __shared__ float warp_sums[8];
    int lane = tid & 31, wid = tid >> 5;
    if (lane == 0) warp_sums[wid] = local;
    __syncthreads();
    if (wid == 0) {
        local = (lane < (blockDim.x >> 5)) ? warp_sums[lane] : 0.0f;
        #pragma unroll
        for (int off = 4; off > 0; off >>= 1)
            local += __shfl_xor_sync(0xFFFFFFFFu, local, off);
        if (lane == 0)
            atomicAdd(out, local * scale);
    }
}

extern "C" void kernel_launch(void* const* d_in, const int* in_sizes, int n_in,
                              void* d_out, int out_size)
{
    // Inputs (metadata order): o (unused), h, t, v
    const float* h = (const float*)d_in[1];
    const float* t = (const float*)d_in[2];
    const int*   v = (const int*)d_in[3];
    float* out = (float*)d_out;

    long long hsize = (long long)in_sizes[1];       // B*NJ*14*14
    long long n4 = hsize / 4;                       // divisible: 196*14*16384
    int npairs = in_sizes[3];                       // B*NJ (v has 1 elem per pair)
    float scale = 2.0f / (float)hsize;              // 1 / (size/2)

    mse_init_kernel<<<1, 32>>>(out);

    const int threads = 256;
    int blocks = 1184;                              // 148 SMs * 8 blocks
    // Ensure coverage of all (b,j) pairs by the single-check path.
    long long total = (long long)blocks * threads;
    if (total < npairs) blocks = (npairs + threads - 1) / threads;

    mse_reduce_kernel<<<blocks, threads>>>(
        (const float4*)h, n4, h, t, v, npairs, scale, out);
}